// round 9
// baseline (speedup 1.0000x reference)
#include <cuda_runtime.h>
#include <cstdint>
#include <math.h>

#define D_DIM   1024
#define T_DIM   50
#define STRIDEQ 10
#define NUM_POS 16
#define MAX_B   4096
#define MAX_KP  13108   /* ceil(131072/10) */

typedef unsigned long long ull;

// ---- device scratch (static; no allocations allowed) ----
__device__ ulonglong2 g_q[MAX_KP];
__device__ ulonglong2 g_a[MAX_B];
__device__ int        g_sel[MAX_B * NUM_POS];
__device__ int        g_cnt[MAX_B];
__device__ float      g_per[MAX_B];
__device__ unsigned   g_counter;

// ------------------------------------------------------------------
// Kernel 1: pack labels (strided queue rows + anchors). Warp per row.
// ------------------------------------------------------------------
__global__ void prep_labels(const int* __restrict__ xlab,
                            const int* __restrict__ qlab,
                            int B, int Kp) {
    if (blockIdx.x == 0 && threadIdx.x == 0) g_counter = 0;
    int warp = (blockIdx.x * blockDim.x + threadIdx.x) >> 5;
    int lane = threadIdx.x & 31;
    if (warp >= Kp + B) return;

    const int* lp = (warp < Kp)
        ? qlab + (long long)warp * STRIDEQ * (T_DIM * 2)
        : xlab + (long long)(warp - Kp) * (T_DIM * 2);

    int2 va = ((const int2*)lp)[lane];
    int l0b = 0, l1b = 0;
    if (32 + lane < T_DIM) {
        int2 vb = ((const int2*)lp)[32 + lane];
        l0b = vb.x; l1b = vb.y;
    }
    unsigned b0lo = __ballot_sync(0xffffffffu, va.x != 0);
    unsigned b1lo = __ballot_sync(0xffffffffu, va.y != 0);
    unsigned b0hi = __ballot_sync(0xffffffffu, l0b != 0);
    unsigned b1hi = __ballot_sync(0xffffffffu, l1b != 0);
    if (lane == 0) {
        ulonglong2 v;
        v.x = (ull)b0lo | ((ull)b0hi << 32);
        v.y = (ull)b1lo | ((ull)b1hi << 32);
        if (warp < Kp) g_q[warp]      = v;
        else           g_a[warp - Kp] = v;
    }
}

// ------------------------------------------------------------------
// Cheap predicate: 2 popcounts, LOP3-friendly masks.
//   mE = same-nonzero-state (axis match OR diag-diag), weight 1
//   mc = mixed diag/axis pair, weight c
// ------------------------------------------------------------------
__device__ __forceinline__ bool pred_fast(
    ull q0, ull q1, ull a0, ull a1, ull da, ull xa, ull orA, float c) {
    ull mE = ~(q0 ^ a0) & ~(q1 ^ a1) & orA;
    ull mc = (da & (q0 ^ q1)) | (xa & (q0 & q1));
    float s = (float)__popcll(mE) + (float)__popcll(mc) * c;
    return s >= 25.0f;
}

// ------------------------------------------------------------------
// Kernel 2: warp-autonomous select. One warp per anchor, no barriers.
// 64 evals per iteration (2 loads in flight), ordered ranks via
// ballot prefix, early exit at 64 granularity.
// ------------------------------------------------------------------
__global__ void __launch_bounds__(128)
select_warp(int B, int Kp) {
    int warp = (blockIdx.x * blockDim.x + threadIdx.x) >> 5;
    int lane = threadIdx.x & 31;
    if (warp >= B) return;
    int b = warp;

    ulonglong2 av = g_a[b];
    ull a0 = av.x, a1 = av.y;
    ull da = a0 & a1, xa = a0 ^ a1, orA = a0 | a1;
    float c = 1.0f / (sqrtf(2.0f) + 1e-8f);
    unsigned lt = (1u << lane) - 1u;

    int total = 0;
#pragma unroll 1
    for (int base = 0; base < Kp; base += 64) {
        int k0 = base + lane;
        int k1 = base + 32 + lane;
        // both loads issued before use (MLP=2)
        ulonglong2 qv0 = g_q[k0 < Kp ? k0 : (Kp - 1)];
        ulonglong2 qv1 = g_q[k1 < Kp ? k1 : (Kp - 1)];
        bool p0 = (k0 < Kp) && pred_fast(qv0.x, qv0.y, a0, a1, da, xa, orA, c);
        bool p1 = (k1 < Kp) && pred_fast(qv1.x, qv1.y, a0, a1, da, xa, orA, c);
        unsigned m0 = __ballot_sync(0xffffffffu, p0);
        unsigned m1 = __ballot_sync(0xffffffffu, p1);

        if (p0) {
            int r = total + __popc(m0 & lt);
            if (r < NUM_POS) g_sel[b * NUM_POS + r] = k0;
        }
        total += __popc(m0);
        if (total < NUM_POS) {
            if (p1) {
                int r = total + __popc(m1 & lt);
                if (r < NUM_POS) g_sel[b * NUM_POS + r] = k1;
            }
            total += __popc(m1);
        }
        if (total >= NUM_POS) break;
    }
    if (lane == 0) g_cnt[b] = (total < NUM_POS) ? total : NUM_POS;
}

// ------------------------------------------------------------------
// Kernel 3: per anchor, 16 gathered dots (norms fused) + loss +
// last-block deterministic mean. (Validated R5 numeric path.)
// ------------------------------------------------------------------
__global__ void __launch_bounds__(512)
loss_kernel(const float* __restrict__ xq, const float* __restrict__ qf,
            float* __restrict__ out, int B) {
    __shared__ float4 s_anchor4[D_DIM / 4];   // 16B aligned
    __shared__ double s_red[512];
    __shared__ float  s_ssq[256];
    __shared__ float  s_loss[NUM_POS];
    __shared__ int    s_last;

    int b    = blockIdx.x;
    int tid  = threadIdx.x;
    int w    = tid >> 5;
    int lane = tid & 31;

    if (tid >= 256) {
        int i = tid - 256;
        float4 v = ((const float4*)(xq + (long long)b * D_DIM))[i];
        s_anchor4[i] = v;
        s_ssq[i] = v.x * v.x + v.y * v.y + v.z * v.z + v.w * v.w;
    }
    __syncthreads();

    int cnt = g_cnt[b];
    float loss = 0.f;
    if (w < cnt) {
        int kp = g_sel[b * NUM_POS + w];
        const float4* pk = (const float4*)(qf + (long long)kp * STRIDEQ * D_DIM);
        const float4* pa = (const float4*)s_anchor4;
        float dot = 0.f, kss = 0.f;
#pragma unroll
        for (int i = 0; i < D_DIM / 4 / 32; i++) {
            float4 a  = pa[lane + i * 32];
            float4 kk = pk[lane + i * 32];
            dot += a.x * kk.x + a.y * kk.y + a.z * kk.z + a.w * kk.w;
            kss += kk.x * kk.x + kk.y * kk.y + kk.z * kk.z + kk.w * kk.w;
        }
#pragma unroll
        for (int o = 16; o; o >>= 1) {
            dot += __shfl_xor_sync(0xffffffffu, dot, o);
            kss += __shfl_xor_sync(0xffffffffu, kss, o);
        }
        float qss = s_ssq[lane] + s_ssq[lane + 32] + s_ssq[lane + 64]
                  + s_ssq[lane + 96] + s_ssq[lane + 128] + s_ssq[lane + 160]
                  + s_ssq[lane + 192] + s_ssq[lane + 224];
#pragma unroll
        for (int o = 16; o; o >>= 1) qss += __shfl_xor_sync(0xffffffffu, qss, o);

        float inv_q = 1.0f / (sqrtf(qss) + 1e-8f);
        float inv_k = 1.0f / (sqrtf(kss) + 1e-8f);
        float s = dot * inv_q * inv_k * 2.0f;     // / TEMPERATURE(0.5)
        float z = -s;                              // -log_sigmoid(s)
        loss = fmaxf(z, 0.f) + log1pf(expf(-fabsf(z)));
    }
    if (lane == 0 && w < NUM_POS) s_loss[w] = loss;
    __syncthreads();

    if (tid == 0) {
        float sum = 0.f;
#pragma unroll
        for (int i = 0; i < NUM_POS; i++) sum += (i < cnt) ? s_loss[i] : 0.f;
        g_per[b] = (cnt > 0) ? (sum / (float)cnt) : 0.f;
        __threadfence();
        unsigned t = atomicAdd(&g_counter, 1u);
        s_last = (t == (unsigned)(gridDim.x - 1)) ? 1 : 0;
    }
    __syncthreads();

    if (s_last) {
        double acc = 0.0;
        for (int i = tid; i < B; i += 512) acc += (double)g_per[i];
        s_red[tid] = acc;
        __syncthreads();
        for (int s = 256; s; s >>= 1) {
            if (tid < s) s_red[tid] += s_red[tid + s];
            __syncthreads();
        }
        if (tid == 0) out[0] = (float)(s_red[0] / (double)B);
    }
}

extern "C" void kernel_launch(void* const* d_in, const int* in_sizes, int n_in,
                              void* d_out, int out_size) {
    const float* xq   = (const float*)d_in[0];
    const int*   xlab = (const int*)  d_in[1];
    const float* qf   = (const float*)d_in[2];
    const int*   qlab = (const int*)  d_in[3];

    int B  = in_sizes[0] / D_DIM;                 // 4096
    int K  = in_sizes[2] / D_DIM;                 // 131072
    int Kp = (K + STRIDEQ - 1) / STRIDEQ;         // 13108

    int warps  = Kp + B;
    int blocks = (warps * 32 + 255) / 256;
    prep_labels<<<blocks, 256>>>(xlab, qlab, B, Kp);
    select_warp<<<(B + 3) / 4, 128>>>(B, Kp);
    loss_kernel<<<B, 512>>>(xq, qf, (float*)d_out, B);
}

// round 10
// speedup vs baseline: 1.3609x; 1.3609x over previous
#include <cuda_runtime.h>
#include <cstdint>
#include <math.h>

#define D_DIM   1024
#define T_DIM   50
#define STRIDEQ 10
#define NUM_POS 16
#define MAX_B   4096
#define MAX_KP  13108   /* ceil(131072/10) */
#define NWMAX   416     /* ceil(13108/32)=410, padded */

typedef unsigned long long ull;

// ---- device scratch (static; no allocations allowed) ----
__device__ ulonglong2 g_q[MAX_KP];
__device__ ulonglong2 g_a[MAX_B];
__device__ int        g_sel[MAX_B * NUM_POS];
__device__ int        g_cnt[MAX_B];
__device__ float      g_per[MAX_B];
__device__ unsigned   g_counter;

// ------------------------------------------------------------------
// Kernel 1: pack labels (strided queue rows + anchors). Warp per row.
// ------------------------------------------------------------------
__global__ void prep_labels(const int* __restrict__ xlab,
                            const int* __restrict__ qlab,
                            int B, int Kp) {
    if (blockIdx.x == 0 && threadIdx.x == 0) g_counter = 0;
    int warp = (blockIdx.x * blockDim.x + threadIdx.x) >> 5;
    int lane = threadIdx.x & 31;
    if (warp >= Kp + B) return;

    const int* lp = (warp < Kp)
        ? qlab + (long long)warp * STRIDEQ * (T_DIM * 2)
        : xlab + (long long)(warp - Kp) * (T_DIM * 2);

    int2 va = ((const int2*)lp)[lane];
    int l0b = 0, l1b = 0;
    if (32 + lane < T_DIM) {
        int2 vb = ((const int2*)lp)[32 + lane];
        l0b = vb.x; l1b = vb.y;
    }
    unsigned b0lo = __ballot_sync(0xffffffffu, va.x != 0);
    unsigned b1lo = __ballot_sync(0xffffffffu, va.y != 0);
    unsigned b0hi = __ballot_sync(0xffffffffu, l0b != 0);
    unsigned b1hi = __ballot_sync(0xffffffffu, l1b != 0);
    if (lane == 0) {
        ulonglong2 v;
        v.x = (ull)b0lo | ((ull)b0hi << 32);
        v.y = (ull)b1lo | ((ull)b1hi << 32);
        if (warp < Kp) g_q[warp]      = v;
        else           g_a[warp - Kp] = v;
    }
}

// ------------------------------------------------------------------
// Cheap predicate (validated R9: rel_err unchanged).
//   mE = same-nonzero-state (axis match OR diag-diag), weight 1
//   mc = mixed diag/axis pair, weight c
// ------------------------------------------------------------------
__device__ __forceinline__ bool pred_fast(
    ull q0, ull q1, ull a0, ull a1, ull da, ull xa, ull orA, float c) {
    ull mE = ~(q0 ^ a0) & ~(q1 ^ a1) & orA;
    ull mc = (da & (q0 ^ q1)) | (xa & (q0 & q1));
    float s = (float)__popcll(mE) + (float)__popcll(mc) * c;
    return s >= 25.0f;
}

// ------------------------------------------------------------------
// Kernel 2: block-per-anchor select. 512 threads; one
// __syncthreads_count (BAR.RED.POPC) per 512 evals gives the exact
// running total with a single barrier. Warp-0 ordered extraction.
// ------------------------------------------------------------------
__global__ void __launch_bounds__(512)
select_block(int B, int Kp) {
    __shared__ unsigned s_words[NWMAX];
    int b    = blockIdx.x;
    int tid  = threadIdx.x;
    int w    = tid >> 5;
    int lane = tid & 31;

    ulonglong2 av = g_a[b];
    ull a0 = av.x, a1 = av.y;
    ull da = a0 & a1, xa = a0 ^ a1, orA = a0 | a1;
    float c = 1.0f / (sqrtf(2.0f) + 1e-8f);

    int total    = 0;
    int scan_end = 0;
#pragma unroll 1
    for (int base = 0; base < Kp; base += 512) {
        int k = base + tid;
        bool pred = false;
        if (k < Kp) {
            ulonglong2 qv = g_q[k];
            pred = pred_fast(qv.x, qv.y, a0, a1, da, xa, orA, c);
        }
        unsigned m = __ballot_sync(0xffffffffu, pred);
        if (lane == 0) s_words[(base >> 5) + w] = m;
        total += __syncthreads_count(pred);   // barrier + exact count
        scan_end = (base + 512 < Kp) ? base + 512 : Kp;
        if (total >= NUM_POS) break;
    }

    // ---- ordered extraction of first <=16 hits (warp 0, validated) ----
    if (w == 0) {
        int nwords = (scan_end + 31) >> 5;
        int run = 0;
        for (int g = 0; g * 32 < nwords && run < NUM_POS; g++) {
            int wi = g * 32 + lane;
            unsigned word = (wi < nwords) ? s_words[wi] : 0u;
            int my = __popc(word);
            int pre = my;
#pragma unroll
            for (int o = 1; o < 32; o <<= 1) {
                int v = __shfl_up_sync(0xffffffffu, pre, o);
                if (lane >= o) pre += v;
            }
            int gtot = __shfl_sync(0xffffffffu, pre, 31);
            int rank = run + pre - my;
            while (word && rank < NUM_POS) {
                int bit = __ffs(word) - 1;
                word &= word - 1;
                g_sel[b * NUM_POS + rank++] = wi * 32 + bit;
            }
            run += gtot;
        }
        if (lane == 0) g_cnt[b] = (total < NUM_POS) ? total : NUM_POS;
    }
}

// ------------------------------------------------------------------
// Kernel 3: per anchor, 16 gathered dots (norms fused) + loss +
// last-block deterministic mean. (Validated numeric path.)
// ------------------------------------------------------------------
__global__ void __launch_bounds__(512)
loss_kernel(const float* __restrict__ xq, const float* __restrict__ qf,
            float* __restrict__ out, int B) {
    __shared__ float4 s_anchor4[D_DIM / 4];   // 16B aligned
    __shared__ double s_red[512];
    __shared__ float  s_ssq[256];
    __shared__ float  s_loss[NUM_POS];
    __shared__ int    s_last;

    int b    = blockIdx.x;
    int tid  = threadIdx.x;
    int w    = tid >> 5;
    int lane = tid & 31;

    if (tid >= 256) {
        int i = tid - 256;
        float4 v = ((const float4*)(xq + (long long)b * D_DIM))[i];
        s_anchor4[i] = v;
        s_ssq[i] = v.x * v.x + v.y * v.y + v.z * v.z + v.w * v.w;
    }
    __syncthreads();

    int cnt = g_cnt[b];
    float loss = 0.f;
    if (w < cnt) {
        int kp = g_sel[b * NUM_POS + w];
        const float4* pk = (const float4*)(qf + (long long)kp * STRIDEQ * D_DIM);
        const float4* pa = (const float4*)s_anchor4;
        float dot = 0.f, kss = 0.f;
#pragma unroll
        for (int i = 0; i < D_DIM / 4 / 32; i++) {
            float4 a  = pa[lane + i * 32];
            float4 kk = pk[lane + i * 32];
            dot += a.x * kk.x + a.y * kk.y + a.z * kk.z + a.w * kk.w;
            kss += kk.x * kk.x + kk.y * kk.y + kk.z * kk.z + kk.w * kk.w;
        }
#pragma unroll
        for (int o = 16; o; o >>= 1) {
            dot += __shfl_xor_sync(0xffffffffu, dot, o);
            kss += __shfl_xor_sync(0xffffffffu, kss, o);
        }
        float qss = s_ssq[lane] + s_ssq[lane + 32] + s_ssq[lane + 64]
                  + s_ssq[lane + 96] + s_ssq[lane + 128] + s_ssq[lane + 160]
                  + s_ssq[lane + 192] + s_ssq[lane + 224];
#pragma unroll
        for (int o = 16; o; o >>= 1) qss += __shfl_xor_sync(0xffffffffu, qss, o);

        float inv_q = 1.0f / (sqrtf(qss) + 1e-8f);
        float inv_k = 1.0f / (sqrtf(kss) + 1e-8f);
        float s = dot * inv_q * inv_k * 2.0f;     // / TEMPERATURE(0.5)
        float z = -s;                              // -log_sigmoid(s)
        loss = fmaxf(z, 0.f) + log1pf(expf(-fabsf(z)));
    }
    if (lane == 0 && w < NUM_POS) s_loss[w] = loss;
    __syncthreads();

    if (tid == 0) {
        float sum = 0.f;
#pragma unroll
        for (int i = 0; i < NUM_POS; i++) sum += (i < cnt) ? s_loss[i] : 0.f;
        g_per[b] = (cnt > 0) ? (sum / (float)cnt) : 0.f;
        __threadfence();
        unsigned t = atomicAdd(&g_counter, 1u);
        s_last = (t == (unsigned)(gridDim.x - 1)) ? 1 : 0;
    }
    __syncthreads();

    if (s_last) {
        double acc = 0.0;
        for (int i = tid; i < B; i += 512) acc += (double)g_per[i];
        s_red[tid] = acc;
        __syncthreads();
        for (int s = 256; s; s >>= 1) {
            if (tid < s) s_red[tid] += s_red[tid + s];
            __syncthreads();
        }
        if (tid == 0) out[0] = (float)(s_red[0] / (double)B);
    }
}

extern "C" void kernel_launch(void* const* d_in, const int* in_sizes, int n_in,
                              void* d_out, int out_size) {
    const float* xq   = (const float*)d_in[0];
    const int*   xlab = (const int*)  d_in[1];
    const float* qf   = (const float*)d_in[2];
    const int*   qlab = (const int*)  d_in[3];

    int B  = in_sizes[0] / D_DIM;                 // 4096
    int K  = in_sizes[2] / D_DIM;                 // 131072
    int Kp = (K + STRIDEQ - 1) / STRIDEQ;         // 13108

    int warps  = Kp + B;
    int blocks = (warps * 32 + 255) / 256;
    prep_labels <<<blocks, 256>>>(xlab, qlab, B, Kp);
    select_block<<<B, 512>>>(B, Kp);
    loss_kernel <<<B, 512>>>(xq, qf, (float*)d_out, B);
}